// round 6
// baseline (speedup 1.0000x reference)
#include <cuda_runtime.h>
#include <cstdint>
#include <math.h>

// Problem dims
#define M_DIM 16
#define VN    8192
#define DIN   512
#define DOUT  512
#define ROWS  (M_DIM * VN)              // 131072
#define NPER  (VN * DIN)                // 4194304 per m-slice
#define NPER4 (NPER / 4)

#define GRAM_CTAS   1024
#define PART_STRIDE 272                 // 256 G partials + 16 sq partials

// -------------------- scratch --------------------
__device__ float g_Wq[(size_t)DOUT * DIN];          // tf32-rounded weights
__device__ float g_Wk[(size_t)DOUT * DIN];
__device__ float g_Wv[(size_t)DOUT * DIN];
__device__ float g_part[GRAM_CTAS * PART_STRIDE];
__device__ float g_P[256];

// -------------------- helpers --------------------
__device__ __forceinline__ uint32_t f2tf(float f) {
    uint32_t u;
    asm("cvt.rna.tf32.f32 %0, %1;" : "=r"(u) : "f"(f));
    return u;
}

__device__ __forceinline__ void mma_tf32(float c[4], const uint32_t a[4],
                                         uint32_t b0, uint32_t b1) {
    asm volatile(
        "mma.sync.aligned.m16n8k8.row.col.f32.tf32.tf32.f32 "
        "{%0,%1,%2,%3}, {%4,%5,%6,%7}, {%8,%9}, {%0,%1,%2,%3};\n"
        : "+f"(c[0]), "+f"(c[1]), "+f"(c[2]), "+f"(c[3])
        : "r"(a[0]), "r"(a[1]), "r"(a[2]), "r"(a[3]), "r"(b0), "r"(b1));
}

__device__ __forceinline__ uint32_t sptr(const void* p) {
    return (uint32_t)__cvta_generic_to_shared(p);
}
__device__ __forceinline__ void cpa16(uint32_t s, const void* g) {
    asm volatile("cp.async.ca.shared.global [%0], [%1], 16;\n" :: "r"(s), "l"(g));
}
#define CP_COMMIT()  asm volatile("cp.async.commit_group;\n")
#define CP_WAIT1()   asm volatile("cp.async.wait_group 1;\n")
#define CP_WAIT0()   asm volatile("cp.async.wait_group 0;\n")

__device__ __forceinline__ void ldsm_x4(uint32_t r[4], uint32_t saddr) {
    asm volatile("ldmatrix.sync.aligned.m8n8.x4.shared.b16 {%0,%1,%2,%3}, [%4];"
        : "=r"(r[0]), "=r"(r[1]), "=r"(r[2]), "=r"(r[3]) : "r"(saddr));
}

// round an A-fragment (raw fp32 bits) to tf32 in-register
__device__ __forceinline__ void rnd_frag(uint32_t a[4]) {
#pragma unroll
    for (int t = 0; t < 4; ++t) a[t] = f2tf(__uint_as_float(a[t]));
}

// -------------------- prep: tf32-round the 3 weight matrices --------------------
__global__ void prep3_kernel(const float4* __restrict__ wq,
                             const float4* __restrict__ wk,
                             const float4* __restrict__ wv)
{
    int i = blockIdx.x * 256 + threadIdx.x;           // 0..65535
    const float4* s = (blockIdx.y == 0) ? wq : (blockIdx.y == 1) ? wk : wv;
    float4* d = (blockIdx.y == 0) ? (float4*)g_Wq
              : (blockIdx.y == 1) ? (float4*)g_Wk : (float4*)g_Wv;
    float4 v = s[i];
    uint4 u = make_uint4(f2tf(v.x), f2tf(v.y), f2tf(v.z), f2tf(v.w));
    d[i] = *(float4*)&u;
}

// ============================================================================
// K1: fused QK projections + Gram + fro. Q/K never hit HBM. X read raw;
// A-fragments rounded in-register post-ldmatrix. Weights pre-rounded.
// ============================================================================
#define K1_QT_OFF    0
#define K1_KT_OFF    17024
#define K1_RED_OFF   34048
#define K1_FLOATS    (34048 + 2304)
#define K1_BYTES     (K1_FLOATS * 4)

__global__ void __launch_bounds__(256) qkgram_kernel(
    const float* __restrict__ X,
    const float* __restrict__ biasq, const float* __restrict__ biask)
{
    extern __shared__ float S[];
    float* QT = S + K1_QT_OFF;      // 128 x 133
    float* KT = S + K1_KT_OFF;      // 128 x 133

    const int tid  = threadIdx.x;
    const int lane = tid & 31;
    const int wid  = tid >> 5;
    const int gid  = lane >> 2;
    const int tig  = lane & 3;
    const int wm   = wid & 3;
    const int wn   = wid >> 2;
    const int v0   = blockIdx.x * 8;

    const int lrow = lane & 15;
    const int lcol = (lane >> 4) << 2;          // 0 or 4
    const int lofs = lrow * 36 + lcol;

    float Gc[2][4] = {{0.f,0.f,0.f,0.f},{0.f,0.f,0.f,0.f}};
    float facc = 0.f;
    float Qa[2][8][4], Ka[2][8][4];

    for (int ct = 0; ct < 4; ++ct) {
        const int n0 = ct * 128;
#pragma unroll
        for (int a = 0; a < 2; a++)
#pragma unroll
            for (int b = 0; b < 8; b++)
#pragma unroll
                for (int c = 0; c < 4; c++) { Qa[a][b][c] = 0.f; Ka[a][b][c] = 0.f; }

        auto issue = [&](int kt, int st) {
            float* dstA = S + st * 13824;
#pragma unroll
            for (int it = 0; it < 4; ++it) {
                int idx = tid + it * 256;
                int r   = idx >> 3;
                int c4  = (idx & 7) << 2;
                int grow = (r >> 3) * VN + v0 + (r & 7);   // gathered (i, v)
                uint32_t sA = sptr(dstA + r * 36 + c4);
                cpa16(sA,            X    + (size_t)grow * DIN     + kt * 32 + c4);
                cpa16(sA + 4608 * 4, g_Wq + (size_t)(n0 + r) * DIN + kt * 32 + c4);
                cpa16(sA + 9216 * 4, g_Wk + (size_t)(n0 + r) * DIN + kt * 32 + c4);
            }
        };

        issue(0, 0); CP_COMMIT();
#pragma unroll 1
        for (int kt = 0; kt < 16; ++kt) {
            if (kt < 15) { issue(kt + 1, (kt + 1) & 1); CP_COMMIT(); CP_WAIT1(); }
            else         { CP_WAIT0(); }
            __syncthreads();
            const uint32_t sA  = sptr(S + (kt & 1) * 13824) + lofs * 4;
            const uint32_t sBq = sA + 4608 * 4;
            const uint32_t sBk = sA + 9216 * 4;
#pragma unroll
            for (int ks = 0; ks < 4; ++ks) {
                const int kb4 = ks * 8 * 4;
                uint32_t af[2][4];
                ldsm_x4(af[0], sA + (wm * 32)      * 144 + kb4);
                ldsm_x4(af[1], sA + (wm * 32 + 16) * 144 + kb4);
                rnd_frag(af[0]); rnd_frag(af[1]);
#pragma unroll
                for (int p = 0; p < 4; ++p) {
                    const uint32_t nofs = (wn * 64 + p * 16) * 144 + kb4;
                    uint32_t qb[4], kbf[4];
                    ldsm_x4(qb,  sBq + nofs);
                    ldsm_x4(kbf, sBk + nofs);
                    mma_tf32(Qa[0][2*p],     af[0], qb[0],  qb[2]);
                    mma_tf32(Qa[1][2*p],     af[1], qb[0],  qb[2]);
                    mma_tf32(Qa[0][2*p + 1], af[0], qb[1],  qb[3]);
                    mma_tf32(Qa[1][2*p + 1], af[1], qb[1],  qb[3]);
                    mma_tf32(Ka[0][2*p],     af[0], kbf[0], kbf[2]);
                    mma_tf32(Ka[1][2*p],     af[1], kbf[0], kbf[2]);
                    mma_tf32(Ka[0][2*p + 1], af[0], kbf[1], kbf[3]);
                    mma_tf32(Ka[1][2*p + 1], af[1], kbf[1], kbf[3]);
                }
            }
            __syncthreads();
        }

        // Epilogue: stage Q/K tiles (+bias), tf32-rounded, into smem
#pragma unroll
        for (int nf = 0; nf < 8; ++nf) {
            int col = wn * 64 + nf * 8 + tig * 2;
            float bq0 = biasq[n0 + col], bq1 = biasq[n0 + col + 1];
            float bk0 = biask[n0 + col], bk1 = biask[n0 + col + 1];
#pragma unroll
            for (int mf = 0; mf < 2; ++mf) {
                int r0 = wm * 32 + mf * 16 + gid;
                QT[r0 * 133 + col]           = __uint_as_float(f2tf(Qa[mf][nf][0] + bq0));
                QT[r0 * 133 + col + 1]       = __uint_as_float(f2tf(Qa[mf][nf][1] + bq1));
                QT[(r0 + 8) * 133 + col]     = __uint_as_float(f2tf(Qa[mf][nf][2] + bq0));
                QT[(r0 + 8) * 133 + col + 1] = __uint_as_float(f2tf(Qa[mf][nf][3] + bq1));
                KT[r0 * 133 + col]           = __uint_as_float(f2tf(Ka[mf][nf][0] + bk0));
                KT[r0 * 133 + col + 1]       = __uint_as_float(f2tf(Ka[mf][nf][1] + bk1));
                KT[(r0 + 8) * 133 + col]     = __uint_as_float(f2tf(Ka[mf][nf][2] + bk0));
                KT[(r0 + 8) * 133 + col + 1] = __uint_as_float(f2tf(Ka[mf][nf][3] + bk1));
            }
        }
        __syncthreads();

        // Gram via MMA: warp `wid` handles dv=wid. Values already tf32 bits.
#pragma unroll
        for (int kk = 0; kk < 16; ++kk) {
            const int kb = kk * 8 + tig;
            uint32_t a[4];
            a[0] = __float_as_uint(QT[(gid * 8 + wid)       * 133 + kb]);
            a[1] = __float_as_uint(QT[((gid + 8) * 8 + wid) * 133 + kb]);
            a[2] = __float_as_uint(QT[(gid * 8 + wid)       * 133 + kb + 4]);
            a[3] = __float_as_uint(QT[((gid + 8) * 8 + wid) * 133 + kb + 4]);
            uint32_t b0 = __float_as_uint(KT[(gid * 8 + wid) * 133 + kb]);
            uint32_t b1 = __float_as_uint(KT[(gid * 8 + wid) * 133 + kb + 4]);
            mma_tf32(Gc[0], a, b0, b1);
            b0 = __float_as_uint(KT[((gid + 8) * 8 + wid) * 133 + kb]);
            b1 = __float_as_uint(KT[((gid + 8) * 8 + wid) * 133 + kb + 4]);
            mma_tf32(Gc[1], a, b0, b1);
        }

        // fro: ||Q||^2 partial
        {
            int r = tid >> 1, cb = (tid & 1) * 64;
#pragma unroll 8
            for (int c = 0; c < 64; ++c) {
                float v = QT[r * 133 + cb + c];
                facc += v * v;
            }
        }
        __syncthreads();
    }

    // Reduce gram fragments across warps -> per-CTA partial
    float* RED = S + K1_RED_OFF;
    RED[wid * 256 + gid * 16 + 2 * tig]               = Gc[0][0];
    RED[wid * 256 + gid * 16 + 2 * tig + 1]           = Gc[0][1];
    RED[wid * 256 + (gid + 8) * 16 + 2 * tig]         = Gc[0][2];
    RED[wid * 256 + (gid + 8) * 16 + 2 * tig + 1]     = Gc[0][3];
    RED[wid * 256 + gid * 16 + 8 + 2 * tig]           = Gc[1][0];
    RED[wid * 256 + gid * 16 + 8 + 2 * tig + 1]       = Gc[1][1];
    RED[wid * 256 + (gid + 8) * 16 + 8 + 2 * tig]     = Gc[1][2];
    RED[wid * 256 + (gid + 8) * 16 + 8 + 2 * tig + 1] = Gc[1][3];
    __syncthreads();
    float g = 0.f;
#pragma unroll
    for (int w = 0; w < 8; ++w) g += RED[w * 256 + tid];
    g_part[(size_t)blockIdx.x * PART_STRIDE + tid] = g;

    float* RED2 = RED + 2048;
    RED2[tid] = facc;
    __syncthreads();
    if (tid < 16) {
        float s = 0.f;
#pragma unroll
        for (int t = 0; t < 16; ++t) s += RED2[tid * 16 + t];
        g_part[(size_t)blockIdx.x * PART_STRIDE + 256 + tid] = s;
    }
}

// ============================================================================
// K2: finalize — reduce partials, sigmoid, dual softmax, 10x projection -> P
// ============================================================================
__global__ void __launch_bounds__(256) finalize_kernel()
{
    __shared__ float Am[256], T[256], FR[256];
    __shared__ float fro[16], m0s[16], s0s[16], m1s[16], s1s[16], red[16], red2[16];
    const int tid = threadIdx.x;
    const int i = tid >> 4, j = tid & 15;

    float a0=0,a1=0,a2=0,a3=0,a4=0,a5=0,a6=0,a7=0;
    for (int c = 0; c < GRAM_CTAS; c += 8) {
        a0 += g_part[(size_t)(c    ) * PART_STRIDE + tid];
        a1 += g_part[(size_t)(c + 1) * PART_STRIDE + tid];
        a2 += g_part[(size_t)(c + 2) * PART_STRIDE + tid];
        a3 += g_part[(size_t)(c + 3) * PART_STRIDE + tid];
        a4 += g_part[(size_t)(c + 4) * PART_STRIDE + tid];
        a5 += g_part[(size_t)(c + 5) * PART_STRIDE + tid];
        a6 += g_part[(size_t)(c + 6) * PART_STRIDE + tid];
        a7 += g_part[(size_t)(c + 7) * PART_STRIDE + tid];
    }
    float g = ((a0 + a1) + (a2 + a3)) + ((a4 + a5) + (a6 + a7));

    {
        float s = 0.f;
        for (int c = i * 64; c < i * 64 + 64; ++c)
            s += g_part[(size_t)c * PART_STRIDE + 256 + j];
        FR[tid] = s;
    }
    __syncthreads();
    if (tid < 16) {
        float s = 0.f;
#pragma unroll
        for (int t = 0; t < 16; ++t) s += FR[t * 16 + tid];
        fro[tid] = sqrtf(s);
    }
    __syncthreads();

    float p0 = 1.f / (1.f + expf(-g / fro[i]));
    Am[tid] = p0;
    __syncthreads();

    if (tid < 16) {
        float m = -1e30f;
        for (int k = 0; k < 16; ++k) m = fmaxf(m, Am[k * 16 + tid]);
        float s = 0.f;
        for (int k = 0; k < 16; ++k) s += expf(Am[k * 16 + tid] - m);
        m0s[tid] = m; s0s[tid] = s;
        float m1 = -1e30f;
        for (int k = 0; k < 16; ++k) m1 = fmaxf(m1, Am[tid * 16 + k]);
        float s1 = 0.f;
        for (int k = 0; k < 16; ++k) s1 += expf(Am[tid * 16 + k] - m1);
        m1s[tid] = m1; s1s[tid] = s1;
    }
    __syncthreads();

    float p = 0.5f * (expf(p0 - m0s[j]) / s0s[j] + expf(p0 - m1s[i]) / s1s[i]);

    for (int it = 0; it < 10; ++it) {
        float p1 = fmaxf(p, 0.f);
        T[tid] = p1;
        __syncthreads();
        if (tid < 16) {
            float s = 0.f;
            for (int k = 0; k < 16; ++k) s += T[tid * 16 + k];
            red[tid] = (s - 1.f) * (1.f / 16.f);
        }
        __syncthreads();
        float p2 = p1 - red[i];
        T[tid] = p2;
        __syncthreads();
        if (tid < 16) {
            float s = 0.f;
            for (int k = 0; k < 16; ++k) s += T[k * 16 + tid];
            red2[tid] = (s - 1.f) * (1.f / 16.f);
        }
        __syncthreads();
        p = p2 - red2[j];
        __syncthreads();
    }
    g_P[tid] = p;
}

// ============================================================================
// K3: fused V-projection + P-mix. out[(j,v),:] = sum_i P[ij] * (X[(i,v),:] Wv^T + bv)
// Gathered tiles (CTA = 8 v x 16 slices). U tile lives only in regs/smem.
// ============================================================================
#define V2_UT_OFF  10240                     // after 2 x 5120 pipeline floats
#define V2_UT_STR  132
#define V2_PS_OFF  (V2_UT_OFF + 128 * V2_UT_STR)
#define V2_FLOATS  (V2_PS_OFF + 256)
#define V2_BYTES   (V2_FLOATS * 4)

__global__ void __launch_bounds__(256) vmix_kernel(
    const float* __restrict__ X, const float* __restrict__ bias,
    float* __restrict__ out)
{
    extern __shared__ float S[];
    float* UT = S + V2_UT_OFF;       // 128 x 132
    float* Ps = S + V2_PS_OFF;       // 256

    const int tid  = threadIdx.x;
    const int lane = tid & 31;
    const int wid  = tid >> 5;
    const int gid  = lane >> 2;
    const int tig  = lane & 3;
    const int wm   = wid & 3;
    const int wn   = wid >> 2;
    const int v0   = blockIdx.x * 8;

    Ps[tid] = g_P[tid];

    const int lrow = lane & 15;
    const int lcol = (lane >> 4) << 2;
    const int lofs = lrow * 20 + lcol;

    for (int ct = 0; ct < 4; ++ct) {
        const int n0 = ct * 128;
        float acc[2][8][4];
#pragma unroll
        for (int a = 0; a < 2; a++)
#pragma unroll
            for (int b = 0; b < 8; b++)
#pragma unroll
                for (int c = 0; c < 4; c++) acc[a][b][c] = 0.f;

        auto issue = [&](int kt, int st) {
            float* dst = S + st * 5120;
#pragma unroll
            for (int it = 0; it < 2; ++it) {
                int idx = tid + it * 256;
                int r   = idx >> 2;
                int c4  = (idx & 3) << 2;
                int grow = (r >> 3) * VN + v0 + (r & 7);
                uint32_t sA = sptr(dst + r * 20 + c4);
                cpa16(sA,            X    + (size_t)grow * DIN     + kt * 16 + c4);
                cpa16(sA + 2560 * 4, g_Wv + (size_t)(n0 + r) * DIN + kt * 16 + c4);
            }
        };

        issue(0, 0); CP_COMMIT();
#pragma unroll 1
        for (int kt = 0; kt < 32; ++kt) {
            if (kt < 31) { issue(kt + 1, (kt + 1) & 1); CP_COMMIT(); CP_WAIT1(); }
            else         { CP_WAIT0(); }
            __syncthreads();
            const uint32_t sA = sptr(S + (kt & 1) * 5120) + lofs * 4;
            const uint32_t sB = sA + 2560 * 4;
#pragma unroll
            for (int ks = 0; ks < 2; ++ks) {
                const int kb4 = ks * 8 * 4;
                uint32_t af[2][4];
                ldsm_x4(af[0], sA + (wm * 32)      * 80 + kb4);
                ldsm_x4(af[1], sA + (wm * 32 + 16) * 80 + kb4);
                rnd_frag(af[0]); rnd_frag(af[1]);
#pragma unroll
                for (int p = 0; p < 4; ++p) {
                    uint32_t bb[4];
                    ldsm_x4(bb, sB + (wn * 64 + p * 16) * 80 + kb4);
                    mma_tf32(acc[0][2*p],     af[0], bb[0], bb[2]);
                    mma_tf32(acc[1][2*p],     af[1], bb[0], bb[2]);
                    mma_tf32(acc[0][2*p + 1], af[0], bb[1], bb[3]);
                    mma_tf32(acc[1][2*p + 1], af[1], bb[1], bb[3]);
                }
            }
            __syncthreads();
        }

        // Stage U tile (+bias) to smem
#pragma unroll
        for (int nf = 0; nf < 8; ++nf) {
            int col = wn * 64 + nf * 8 + tig * 2;
            float b0 = bias[n0 + col];
            float b1 = bias[n0 + col + 1];
#pragma unroll
            for (int mf = 0; mf < 2; ++mf) {
                int r0 = wm * 32 + mf * 16 + gid;
                *(float2*)&UT[r0 * V2_UT_STR + col] =
                    make_float2(acc[mf][nf][0] + b0, acc[mf][nf][1] + b1);
                *(float2*)&UT[(r0 + 8) * V2_UT_STR + col] =
                    make_float2(acc[mf][nf][2] + b0, acc[mf][nf][3] + b1);
            }
        }
        __syncthreads();

        // P-mix epilogue: warp handles 16 output rows; lane = float4 column
#pragma unroll 1
        for (int rr = 0; rr < 16; ++rr) {
            int R  = wid * 16 + rr;      // gathered out row
            int vv = R & 7;
            int j  = R >> 3;
            float4 y = make_float4(0.f, 0.f, 0.f, 0.f);
#pragma unroll
            for (int i = 0; i < 16; ++i) {
                float pv = Ps[i * 16 + j];
                float4 u = *(const float4*)&UT[(i * 8 + vv) * V2_UT_STR + lane * 4];
                y.x += pv * u.x; y.y += pv * u.y; y.z += pv * u.z; y.w += pv * u.w;
            }
            *(float4*)(out + (size_t)(j * VN + v0 + vv) * DOUT + n0 + lane * 4) = y;
        }
        __syncthreads();
    }
}

// -------------------- launch --------------------
extern "C" void kernel_launch(void* const* d_in, const int* in_sizes, int n_in,
                              void* d_out, int out_size)
{
    const float* X   = (const float*)d_in[0];
    const float* WQw = (const float*)d_in[1];
    const float* WQb = (const float*)d_in[2];
    const float* WKw = (const float*)d_in[3];
    const float* WKb = (const float*)d_in[4];
    const float* WVw = (const float*)d_in[5];
    const float* WVb = (const float*)d_in[6];
    float* out = (float*)d_out;

    cudaFuncSetAttribute(qkgram_kernel,
                         cudaFuncAttributeMaxDynamicSharedMemorySize, K1_BYTES);
    cudaFuncSetAttribute(vmix_kernel,
                         cudaFuncAttributeMaxDynamicSharedMemorySize, V2_BYTES);

    // tf32-round the three weight matrices (X stays raw; rounded in-register)
    prep3_kernel<<<dim3(256, 3), 256>>>((const float4*)WQw,
                                        (const float4*)WKw,
                                        (const float4*)WVw);

    // Fused Q/K projections + Gram + fro
    qkgram_kernel<<<GRAM_CTAS, 256, K1_BYTES>>>(X, WQb, WKb);

    // P (only needs qkgram)
    finalize_kernel<<<1, 256>>>();

    // Fused V projection + P mix (U never materialized)
    vmix_kernel<<<GRAM_CTAS, 256, V2_BYTES>>>(X, WVb, out);
}

// round 7
// speedup vs baseline: 1.0981x; 1.0981x over previous
#include <cuda_runtime.h>
#include <cstdint>
#include <math.h>

// Problem dims
#define M_DIM 16
#define VN    8192
#define DIN   512
#define DOUT  512
#define ROWS  (M_DIM * VN)              // 131072
#define NPER  (VN * DIN)                // 4194304 per m-slice
#define NPER4 (NPER / 4)

#define GRAM_CTAS   1024
#define PART_STRIDE 272                 // 256 G partials + 16 sq partials

// -------------------- scratch --------------------
__device__ float g_Wq[(size_t)DOUT * DIN];          // tf32-rounded weights
__device__ float g_Wk[(size_t)DOUT * DIN];
__device__ float g_Wv[(size_t)DOUT * DIN];
__device__ float g_U[(size_t)ROWS * DOUT];          // U = X Wv^T + bv
__device__ float g_part[GRAM_CTAS * PART_STRIDE];
__device__ float g_P[256];

// -------------------- helpers --------------------
__device__ __forceinline__ uint32_t f2tf(float f) {
    uint32_t u;
    asm("cvt.rna.tf32.f32 %0, %1;" : "=r"(u) : "f"(f));
    return u;
}

__device__ __forceinline__ void mma_tf32(float c[4], const uint32_t a[4],
                                         uint32_t b0, uint32_t b1) {
    asm volatile(
        "mma.sync.aligned.m16n8k8.row.col.f32.tf32.tf32.f32 "
        "{%0,%1,%2,%3}, {%4,%5,%6,%7}, {%8,%9}, {%0,%1,%2,%3};\n"
        : "+f"(c[0]), "+f"(c[1]), "+f"(c[2]), "+f"(c[3])
        : "r"(a[0]), "r"(a[1]), "r"(a[2]), "r"(a[3]), "r"(b0), "r"(b1));
}

__device__ __forceinline__ uint32_t sptr(const void* p) {
    return (uint32_t)__cvta_generic_to_shared(p);
}
__device__ __forceinline__ void cpa16(uint32_t s, const void* g) {
    asm volatile("cp.async.ca.shared.global [%0], [%1], 16;\n" :: "r"(s), "l"(g));
}
#define CP_COMMIT()  asm volatile("cp.async.commit_group;\n")
#define CP_WAIT1()   asm volatile("cp.async.wait_group 1;\n")
#define CP_WAIT0()   asm volatile("cp.async.wait_group 0;\n")

__device__ __forceinline__ void ldsm_x4(uint32_t r[4], uint32_t saddr) {
    asm volatile("ldmatrix.sync.aligned.m8n8.x4.shared.b16 {%0,%1,%2,%3}, [%4];"
        : "=r"(r[0]), "=r"(r[1]), "=r"(r[2]), "=r"(r[3]) : "r"(saddr));
}

__device__ __forceinline__ void rnd_frag(uint32_t a[4]) {
#pragma unroll
    for (int t = 0; t < 4; ++t) a[t] = f2tf(__uint_as_float(a[t]));
}

// -------------------- prep: tf32-round the 3 weight matrices --------------------
__global__ void prep3_kernel(const float4* __restrict__ wq,
                             const float4* __restrict__ wk,
                             const float4* __restrict__ wv)
{
    int i = blockIdx.x * 256 + threadIdx.x;           // 0..65535
    const float4* s = (blockIdx.y == 0) ? wq : (blockIdx.y == 1) ? wk : wv;
    float4* d = (blockIdx.y == 0) ? (float4*)g_Wq
              : (blockIdx.y == 1) ? (float4*)g_Wk : (float4*)g_Wv;
    float4 v = s[i];
    uint4 u = make_uint4(f2tf(v.x), f2tf(v.y), f2tf(v.z), f2tf(v.w));
    d[i] = *(float4*)&u;
}

// ============================================================================
// K1: fused QK projections + Gram + fro, 512 threads.
// Warp-group 0 (warps 0-7) computes Q-tile, group 1 (8-15) computes K-tile;
// 3-stage cp.async pipeline (stages overlap QT/KT staging area).
// smem: 3 stages x (A[128x36] + Bq[128x36] + Bk[128x36]) = 41472 floats.
//   QT = [0,17024), KT = [17024,34048), RED = [34048,36096), RED2 = [36096,36352)
// ============================================================================
#define K1_STAGE   13824
#define K1_KT_OFF  17024
#define K1_RED_OFF 34048
#define K1_FLOATS  (3 * K1_STAGE)
#define K1_BYTES   (K1_FLOATS * 4)

__global__ void __launch_bounds__(512, 1) qkgram_kernel(
    const float* __restrict__ X,
    const float* __restrict__ biasq, const float* __restrict__ biask)
{
    extern __shared__ float S[];
    float* QT = S;
    float* KT = S + K1_KT_OFF;

    const int tid  = threadIdx.x;
    const int lane = tid & 31;
    const int wid  = tid >> 5;      // 0..15
    const int wg   = wid >> 3;      // 0 = Q group, 1 = K group
    const int wl   = wid & 7;       // warp within group
    const int gid  = lane >> 2;
    const int tig  = lane & 3;
    const int wm   = wl & 3;        // 4 m-tiles of 32 rows
    const int wn   = wl >> 2;       // 2 n-tiles of 64 cols
    const int v0   = blockIdx.x * 8;

    const int lofs = (lane & 15) * 36 + ((lane >> 4) << 2);

    const float* bias = wg ? biask : biasq;
    float*       OT   = wg ? KT : QT;

    float Gc[2][4] = {{0.f,0.f,0.f,0.f},{0.f,0.f,0.f,0.f}};
    float facc = 0.f;
    float acc[2][8][4];

    for (int ct = 0; ct < 4; ++ct) {
        const int n0 = ct * 128;
#pragma unroll
        for (int a = 0; a < 2; a++)
#pragma unroll
            for (int b = 0; b < 8; b++)
#pragma unroll
                for (int c = 0; c < 4; c++) acc[a][b][c] = 0.f;

        auto issue = [&](int kt, int st) {
            float* dstA = S + st * K1_STAGE;
#pragma unroll
            for (int it = 0; it < 2; ++it) {
                int idx = tid + it * 512;          // 0..1023 float4 slots
                int r   = idx >> 3;
                int c4  = (idx & 7) << 2;
                int grow = (r >> 3) * VN + v0 + (r & 7);
                uint32_t sA = sptr(dstA + r * 36 + c4);
                cpa16(sA,            X    + (size_t)grow * DIN     + kt * 32 + c4);
                cpa16(sA + 4608 * 4, g_Wq + (size_t)(n0 + r) * DIN + kt * 32 + c4);
                cpa16(sA + 9216 * 4, g_Wk + (size_t)(n0 + r) * DIN + kt * 32 + c4);
            }
        };

        issue(0, 0); CP_COMMIT();
        issue(1, 1); CP_COMMIT();
#pragma unroll 1
        for (int kt = 0; kt < 16; ++kt) {
            if (kt < 14) { CP_WAIT1(); } else { CP_WAIT0(); }
            __syncthreads();
            if (kt + 2 < 16) { issue(kt + 2, (kt + 2) % 3); CP_COMMIT(); }
            const uint32_t sA = sptr(S + (kt % 3) * K1_STAGE) + lofs * 4;
            const uint32_t sB = sA + (wg ? 9216 : 4608) * 4;
#pragma unroll
            for (int ks = 0; ks < 4; ++ks) {
                const int kb4 = ks * 32;
                uint32_t af[2][4];
                ldsm_x4(af[0], sA + (wm * 32)      * 144 + kb4);
                ldsm_x4(af[1], sA + (wm * 32 + 16) * 144 + kb4);
                rnd_frag(af[0]); rnd_frag(af[1]);
#pragma unroll
                for (int p = 0; p < 4; ++p) {
                    uint32_t bb[4];
                    ldsm_x4(bb, sB + (wn * 64 + p * 16) * 144 + kb4);
                    mma_tf32(acc[0][2*p],     af[0], bb[0], bb[2]);
                    mma_tf32(acc[1][2*p],     af[1], bb[0], bb[2]);
                    mma_tf32(acc[0][2*p + 1], af[0], bb[1], bb[3]);
                    mma_tf32(acc[1][2*p + 1], af[1], bb[1], bb[3]);
                }
            }
        }
        __syncthreads();   // all compute done before staging over pipeline bufs

        // Stage this group's projected tile (+bias), tf32-rounded
#pragma unroll
        for (int nf = 0; nf < 8; ++nf) {
            int col = wn * 64 + nf * 8 + tig * 2;
            float b0 = bias[n0 + col], b1 = bias[n0 + col + 1];
#pragma unroll
            for (int mf = 0; mf < 2; ++mf) {
                int r0 = wm * 32 + mf * 16 + gid;
                OT[r0 * 133 + col]           = __uint_as_float(f2tf(acc[mf][nf][0] + b0));
                OT[r0 * 133 + col + 1]       = __uint_as_float(f2tf(acc[mf][nf][1] + b1));
                OT[(r0 + 8) * 133 + col]     = __uint_as_float(f2tf(acc[mf][nf][2] + b0));
                OT[(r0 + 8) * 133 + col + 1] = __uint_as_float(f2tf(acc[mf][nf][3] + b1));
            }
        }
        __syncthreads();

        if (wg == 0) {
            // Gram via MMA: Q-warp wl handles dv=wl
#pragma unroll
            for (int kk = 0; kk < 16; ++kk) {
                const int kb = kk * 8 + tig;
                uint32_t a[4];
                a[0] = __float_as_uint(QT[(gid * 8 + wl)       * 133 + kb]);
                a[1] = __float_as_uint(QT[((gid + 8) * 8 + wl) * 133 + kb]);
                a[2] = __float_as_uint(QT[(gid * 8 + wl)       * 133 + kb + 4]);
                a[3] = __float_as_uint(QT[((gid + 8) * 8 + wl) * 133 + kb + 4]);
                uint32_t b0 = __float_as_uint(KT[(gid * 8 + wl) * 133 + kb]);
                uint32_t b1 = __float_as_uint(KT[(gid * 8 + wl) * 133 + kb + 4]);
                mma_tf32(Gc[0], a, b0, b1);
                b0 = __float_as_uint(KT[((gid + 8) * 8 + wl) * 133 + kb]);
                b1 = __float_as_uint(KT[((gid + 8) * 8 + wl) * 133 + kb + 4]);
                mma_tf32(Gc[1], a, b0, b1);
            }
        } else {
            // fro: ||Q||^2 partial, K-group's 256 threads cover 128 rows x 2 halves
            int t = tid - 256;
            int r = t >> 1, cb = (t & 1) * 64;
#pragma unroll 8
            for (int c = 0; c < 64; ++c) {
                float v = QT[r * 133 + cb + c];
                facc += v * v;
            }
        }
        __syncthreads();
    }

    // Reduce gram fragments (Q-warps) + fro partials (K-warps)
    float* RED  = S + K1_RED_OFF;
    float* RED2 = RED + 2048;
    if (wg == 0) {
        RED[wl * 256 + gid * 16 + 2 * tig]               = Gc[0][0];
        RED[wl * 256 + gid * 16 + 2 * tig + 1]           = Gc[0][1];
        RED[wl * 256 + (gid + 8) * 16 + 2 * tig]         = Gc[0][2];
        RED[wl * 256 + (gid + 8) * 16 + 2 * tig + 1]     = Gc[0][3];
        RED[wl * 256 + gid * 16 + 8 + 2 * tig]           = Gc[1][0];
        RED[wl * 256 + gid * 16 + 8 + 2 * tig + 1]       = Gc[1][1];
        RED[wl * 256 + (gid + 8) * 16 + 8 + 2 * tig]     = Gc[1][2];
        RED[wl * 256 + (gid + 8) * 16 + 8 + 2 * tig + 1] = Gc[1][3];
    } else {
        RED2[tid - 256] = facc;
    }
    __syncthreads();
    if (tid < 256) {
        float g = 0.f;
#pragma unroll
        for (int w = 0; w < 8; ++w) g += RED[w * 256 + tid];
        g_part[(size_t)blockIdx.x * PART_STRIDE + tid] = g;
    }
    if (tid < 16) {
        float s = 0.f;
#pragma unroll
        for (int t = 0; t < 16; ++t) s += RED2[tid * 16 + t];
        g_part[(size_t)blockIdx.x * PART_STRIDE + 256 + tid] = s;
    }
}

// ============================================================================
// K2: U = X Wv^T + bv  (k-tile 32, 3-stage cp.async, 2 CTAs/SM)
// ============================================================================
#define V_STAGE  9216
#define V_BYTES  (3 * V_STAGE * 4)

__global__ void __launch_bounds__(256, 2) gemm_v(
    const float* __restrict__ X, const float* __restrict__ bias)
{
    extern __shared__ float S[];

    const int tid  = threadIdx.x;
    const int lane = tid & 31;
    const int wid  = tid >> 5;
    const int gid  = lane >> 2;
    const int tig  = lane & 3;
    const int wm   = wid & 3;
    const int wn   = wid >> 2;
    const int m0   = blockIdx.y * 128;
    const int n0   = blockIdx.x * 128;

    const int lofs = (lane & 15) * 36 + ((lane >> 4) << 2);

    float acc[2][8][4];
#pragma unroll
    for (int a = 0; a < 2; a++)
#pragma unroll
        for (int b = 0; b < 8; b++)
#pragma unroll
            for (int c = 0; c < 4; c++) acc[a][b][c] = 0.f;

    auto issue = [&](int kt, int st) {
        float* dst = S + st * V_STAGE;
#pragma unroll
        for (int it = 0; it < 4; ++it) {
            int idx = tid + it * 256;          // 0..1023 float4 slots
            int r   = idx >> 3;
            int c4  = (idx & 7) << 2;
            uint32_t sA = sptr(dst + r * 36 + c4);
            cpa16(sA,            X    + (size_t)(m0 + r) * DIN + kt * 32 + c4);
            cpa16(sA + 4608 * 4, g_Wv + (size_t)(n0 + r) * DIN + kt * 32 + c4);
        }
    };

    issue(0, 0); CP_COMMIT();
    issue(1, 1); CP_COMMIT();
#pragma unroll 1
    for (int kt = 0; kt < 16; ++kt) {
        if (kt < 14) { CP_WAIT1(); } else { CP_WAIT0(); }
        __syncthreads();
        if (kt + 2 < 16) { issue(kt + 2, (kt + 2) % 3); CP_COMMIT(); }
        const uint32_t sA = sptr(S + (kt % 3) * V_STAGE) + lofs * 4;
        const uint32_t sB = sA + 4608 * 4;
#pragma unroll
        for (int ks = 0; ks < 4; ++ks) {
            const int kb4 = ks * 32;
            uint32_t af[2][4];
            ldsm_x4(af[0], sA + (wm * 32)      * 144 + kb4);
            ldsm_x4(af[1], sA + (wm * 32 + 16) * 144 + kb4);
            rnd_frag(af[0]); rnd_frag(af[1]);
#pragma unroll
            for (int p = 0; p < 4; ++p) {
                uint32_t bb[4];
                ldsm_x4(bb, sB + (wn * 64 + p * 16) * 144 + kb4);
                mma_tf32(acc[0][2*p],     af[0], bb[0], bb[2]);
                mma_tf32(acc[1][2*p],     af[1], bb[0], bb[2]);
                mma_tf32(acc[0][2*p + 1], af[0], bb[1], bb[3]);
                mma_tf32(acc[1][2*p + 1], af[1], bb[1], bb[3]);
            }
        }
    }

#pragma unroll
    for (int nf = 0; nf < 8; ++nf) {
        int col = n0 + wn * 64 + nf * 8 + tig * 2;
        float b0 = bias[col];
        float b1 = bias[col + 1];
#pragma unroll
        for (int mf = 0; mf < 2; ++mf) {
            int r0 = m0 + wm * 32 + mf * 16 + gid;
            *(float2*)(g_U + (size_t)r0 * DOUT + col) =
                make_float2(acc[mf][nf][0] + b0, acc[mf][nf][1] + b1);
            *(float2*)(g_U + (size_t)(r0 + 8) * DOUT + col) =
                make_float2(acc[mf][nf][2] + b0, acc[mf][nf][3] + b1);
        }
    }
}

// ============================================================================
// K3: finalize — reduce partials, sigmoid, dual softmax, 10x projection -> P
// ============================================================================
__global__ void __launch_bounds__(256) finalize_kernel()
{
    __shared__ float Am[256], T[256], FR[256];
    __shared__ float fro[16], m0s[16], s0s[16], m1s[16], s1s[16], red[16], red2[16];
    const int tid = threadIdx.x;
    const int i = tid >> 4, j = tid & 15;

    float a0=0,a1=0,a2=0,a3=0,a4=0,a5=0,a6=0,a7=0;
    for (int c = 0; c < GRAM_CTAS; c += 8) {
        a0 += g_part[(size_t)(c    ) * PART_STRIDE + tid];
        a1 += g_part[(size_t)(c + 1) * PART_STRIDE + tid];
        a2 += g_part[(size_t)(c + 2) * PART_STRIDE + tid];
        a3 += g_part[(size_t)(c + 3) * PART_STRIDE + tid];
        a4 += g_part[(size_t)(c + 4) * PART_STRIDE + tid];
        a5 += g_part[(size_t)(c + 5) * PART_STRIDE + tid];
        a6 += g_part[(size_t)(c + 6) * PART_STRIDE + tid];
        a7 += g_part[(size_t)(c + 7) * PART_STRIDE + tid];
    }
    float g = ((a0 + a1) + (a2 + a3)) + ((a4 + a5) + (a6 + a7));

    {
        float s = 0.f;
        for (int c = i * 64; c < i * 64 + 64; ++c)
            s += g_part[(size_t)c * PART_STRIDE + 256 + j];
        FR[tid] = s;
    }
    __syncthreads();
    if (tid < 16) {
        float s = 0.f;
#pragma unroll
        for (int t = 0; t < 16; ++t) s += FR[t * 16 + tid];
        fro[tid] = sqrtf(s);
    }
    __syncthreads();

    float p0 = 1.f / (1.f + expf(-g / fro[i]));
    Am[tid] = p0;
    __syncthreads();

    if (tid < 16) {
        float m = -1e30f;
        for (int k = 0; k < 16; ++k) m = fmaxf(m, Am[k * 16 + tid]);
        float s = 0.f;
        for (int k = 0; k < 16; ++k) s += expf(Am[k * 16 + tid] - m);
        m0s[tid] = m; s0s[tid] = s;
        float m1 = -1e30f;
        for (int k = 0; k < 16; ++k) m1 = fmaxf(m1, Am[tid * 16 + k]);
        float s1 = 0.f;
        for (int k = 0; k < 16; ++k) s1 += expf(Am[tid * 16 + k] - m1);
        m1s[tid] = m1; s1s[tid] = s1;
    }
    __syncthreads();

    float p = 0.5f * (expf(p0 - m0s[j]) / s0s[j] + expf(p0 - m1s[i]) / s1s[i]);

    for (int it = 0; it < 10; ++it) {
        float p1 = fmaxf(p, 0.f);
        T[tid] = p1;
        __syncthreads();
        if (tid < 16) {
            float s = 0.f;
            for (int k = 0; k < 16; ++k) s += T[tid * 16 + k];
            red[tid] = (s - 1.f) * (1.f / 16.f);
        }
        __syncthreads();
        float p2 = p1 - red[i];
        T[tid] = p2;
        __syncthreads();
        if (tid < 16) {
            float s = 0.f;
            for (int k = 0; k < 16; ++k) s += T[k * 16 + tid];
            red2[tid] = (s - 1.f) * (1.f / 16.f);
        }
        __syncthreads();
        p = p2 - red2[j];
        __syncthreads();
    }
    g_P[tid] = p;
}

// ============================================================================
// K4: out[j] = sum_i P[i,j] * U[i]
// ============================================================================
__global__ void __launch_bounds__(256) mix_kernel(float* __restrict__ out)
{
    __shared__ float Ps[256];
    Ps[threadIdx.x] = g_P[threadIdx.x];
    __syncthreads();

    size_t n4 = (size_t)blockIdx.x * 256 + threadIdx.x;
    const float4* U4 = (const float4*)g_U;
    float4* O4 = (float4*)out;

    float4 x[16];
#pragma unroll
    for (int i = 0; i < 16; ++i) x[i] = U4[(size_t)i * NPER4 + n4];
#pragma unroll
    for (int jj = 0; jj < 16; ++jj) {
        float4 y = make_float4(0.f, 0.f, 0.f, 0.f);
#pragma unroll
        for (int i = 0; i < 16; ++i) {
            float pv = Ps[i * 16 + jj];
            y.x += pv * x[i].x; y.y += pv * x[i].y;
            y.z += pv * x[i].z; y.w += pv * x[i].w;
        }
        O4[(size_t)jj * NPER4 + n4] = y;
    }
}

// -------------------- launch --------------------
extern "C" void kernel_launch(void* const* d_in, const int* in_sizes, int n_in,
                              void* d_out, int out_size)
{
    const float* X   = (const float*)d_in[0];
    const float* WQw = (const float*)d_in[1];
    const float* WQb = (const float*)d_in[2];
    const float* WKw = (const float*)d_in[3];
    const float* WKb = (const float*)d_in[4];
    const float* WVw = (const float*)d_in[5];
    const float* WVb = (const float*)d_in[6];
    float* out = (float*)d_out;

    cudaFuncSetAttribute(qkgram_kernel,
                         cudaFuncAttributeMaxDynamicSharedMemorySize, K1_BYTES);
    cudaFuncSetAttribute(gemm_v,
                         cudaFuncAttributeMaxDynamicSharedMemorySize, V_BYTES);

    // tf32-round the three weight matrices (X stays raw; rounded in-register)
    prep3_kernel<<<dim3(256, 3), 256>>>((const float4*)WQw,
                                        (const float4*)WKw,
                                        (const float4*)WVw);

    // Fused Q/K projections + Gram + fro (512 thr: Q-warps + K-warps)
    qkgram_kernel<<<GRAM_CTAS, 512, K1_BYTES>>>(X, WQb, WKb);

    // U = X Wv^T + bv
    gemm_v<<<dim3(DOUT / 128, ROWS / 128), 256, V_BYTES>>>(X, WVb);

    // P
    finalize_kernel<<<1, 256>>>();

    // out[j] = sum_i P[ij] U[i]
    mix_kernel<<<NPER4 / 256, 256>>>(out);
}